// round 3
// baseline (speedup 1.0000x reference)
#include <cuda_runtime.h>
#include <cuda_bf16.h>
#include <math.h>
#include <stdint.h>

#define Cc   256
#define Hh   128
#define Wwid 128
#define HW   16384
#define CHW  4194304
#define Bb   8
#define NBLK 128

// ---------------- static scratch ----------------
__device__ __align__(1024) float  g_bufA[(size_t)Bb * CHW];
__device__ __align__(1024) float  g_bufB[(size_t)Bb * CHW];
__device__ __align__(1024) float  g_bufX1[(size_t)Bb * CHW];
__device__ __align__(1024) __nv_bfloat16 g_XcA[(size_t)Bb * HW * 512];
__device__ __align__(1024) __nv_bfloat16 g_XcB[(size_t)Bb * HW * 512];
__device__ __align__(1024) __nv_bfloat16 g_Abuf[(size_t)Bb * 256 * 512];
__device__ float  g_bias2[Bb * Cc];
__device__ double g_part[Bb * NBLK * 2];
__device__ float  g_ppart[(size_t)Bb * Cc * 256];
__device__ float  g_scale[Bb * Cc];
__device__ float  g_shift[Bb * Cc];
__device__ float  g_att[Bb * Cc];

__device__ __forceinline__ float gelu1(float x) {
    return 0.5f * x * (1.0f + erff(x * 0.70710678118654752440f));
}

// ---------------- PTX helpers ----------------
__device__ __forceinline__ uint32_t smem_u32(const void* p) {
    uint32_t a;
    asm("{ .reg .u64 t; cvta.to.shared.u64 t, %1; cvt.u32.u64 %0, t; }" : "=r"(a) : "l"(p));
    return a;
}
#define SWZ128(off) ((off) ^ (((off) >> 3) & 0x70))
#define CP_ASYNC16(sa, g) asm volatile("cp.async.cg.shared.global [%0], [%1], 16;" :: "r"(sa), "l"(g) : "memory")
#define CP_COMMIT() asm volatile("cp.async.commit_group;" ::: "memory")
#define CP_WAIT1()  asm volatile("cp.async.wait_group 1;" ::: "memory")
#define CP_WAIT0()  asm volatile("cp.async.wait_group 0;" ::: "memory")

__device__ __forceinline__ void ldsm4(uint32_t& r0, uint32_t& r1, uint32_t& r2, uint32_t& r3,
                                      uint32_t a) {
    asm volatile("ldmatrix.sync.aligned.m8n8.x4.shared.b16 {%0,%1,%2,%3}, [%4];"
                 : "=r"(r0), "=r"(r1), "=r"(r2), "=r"(r3) : "r"(a));
}
__device__ __forceinline__ void mma16816(float* c, uint32_t a0, uint32_t a1, uint32_t a2,
                                         uint32_t a3, uint32_t b0, uint32_t b1) {
    asm volatile("mma.sync.aligned.m16n8k16.row.col.f32.bf16.bf16.f32 "
                 "{%0,%1,%2,%3}, {%4,%5,%6,%7}, {%8,%9}, {%0,%1,%2,%3};"
                 : "+f"(c[0]), "+f"(c[1]), "+f"(c[2]), "+f"(c[3])
                 : "r"(a0), "r"(a1), "r"(a2), "r"(a3), "r"(b0), "r"(b1));
}

// ---------------- stats ----------------
__global__ void __launch_bounds__(256) stats1_k(const float* __restrict__ in,
                                                double* __restrict__ part) {
    int b = blockIdx.y, blk = blockIdx.x, t = threadIdx.x;
    size_t base = (size_t)b * CHW + (size_t)blk * (CHW / NBLK);
    double s = 0.0, s2 = 0.0;
    for (int i = t; i < CHW / NBLK; i += 256) {
        float x = in[base + i];
        s += (double)x; s2 += (double)x * (double)x;
    }
    __shared__ double ss[256], ss2[256];
    ss[t] = s; ss2[t] = s2;
    __syncthreads();
    for (int off = 128; off > 0; off >>= 1) {
        if (t < off) { ss[t] += ss[t + off]; ss2[t] += ss2[t + off]; }
        __syncthreads();
    }
    if (t == 0) {
        part[(b * NBLK + blk) * 2 + 0] = ss[0];
        part[(b * NBLK + blk) * 2 + 1] = ss2[0];
    }
}

__global__ void __launch_bounds__(256) stats2_k(const double* __restrict__ part,
                                                const float* __restrict__ gw,
                                                const float* __restrict__ gb,
                                                float* __restrict__ scale,
                                                float* __restrict__ shift) {
    int b = blockIdx.x, t = threadIdx.x;
    __shared__ double ss[128], ss2[128];
    __shared__ float smean, srstd;
    if (t < 128) {
        ss[t]  = part[(b * NBLK + t) * 2 + 0];
        ss2[t] = part[(b * NBLK + t) * 2 + 1];
    }
    __syncthreads();
    for (int off = 64; off > 0; off >>= 1) {
        if (t < off) { ss[t] += ss[t + off]; ss2[t] += ss2[t + off]; }
        __syncthreads();
    }
    if (t == 0) {
        double m = ss[0] / (double)CHW;
        double v = ss2[0] / (double)CHW - m * m;
        smean = (float)m;
        srstd = rsqrtf((float)v + 1e-5f);
    }
    __syncthreads();
    float sc = srstd * gw[t];
    scale[b * Cc + t] = sc;
    shift[b * Cc + t] = gb[t] - smean * sc;
}

// ---------------- prep: (optional gelu^2 + grouped 1x1) -> transpose -> bf16 split
__global__ void __launch_bounds__(256) prep_k(const float* __restrict__ in,
                                              const float* __restrict__ wg,
                                              const float* __restrict__ bg,
                                              __nv_bfloat16* __restrict__ out,
                                              float* __restrict__ ppart,
                                              int do_gelu) {
    extern __shared__ __align__(16) char sm[];
    char* ot = sm;                              // 64 rows x 1028 bytes
    float* xs = (float*)(sm + 64 * 1028);       // 4*64 floats
    float* sacc = xs + 256;                     // 512 floats
    int t = threadIdx.x;
    int b = blockIdx.y, pt = blockIdx.x;
    int p0 = pt * 64;
    int cl = t >> 6, pp = t & 63;
    size_t ibase = (size_t)b * CHW + p0;

    for (int g = 0; g < 64; g++) {
        int c = g * 4 + cl;
        float x = in[ibase + (size_t)c * HW + pp];
        float v = do_gelu ? gelu1(gelu1(x)) : x;
        float u;
        if (wg) {
            xs[cl * 64 + pp] = v;
            __syncthreads();
            u = __ldg(&bg[c]);
#pragma unroll
            for (int i = 0; i < 4; i++) u += __ldg(&wg[g * 16 + cl * 4 + i]) * xs[i * 64 + pp];
            __syncthreads();
        } else {
            u = v;
        }
        __nv_bfloat16 hi = __float2bfloat16(u);
        __nv_bfloat16 lo = __float2bfloat16(u - __bfloat162float(hi));
        *(__nv_bfloat16*)(ot + pp * 1028 + c * 2) = hi;
        *(__nv_bfloat16*)(ot + pp * 1028 + (256 + c) * 2) = lo;
        if (ppart) {
            float s = u;
#pragma unroll
            for (int off = 16; off > 0; off >>= 1) s += __shfl_down_sync(0xffffffffu, s, off);
            if ((t & 31) == 0) sacc[c * 2 + ((t >> 5) & 1)] = s;
        }
    }
    __syncthreads();
    uint32_t* og = (uint32_t*)out;
    for (int w = t; w < 16384; w += 256) {
        int r = w >> 8, ww = w & 255;
        og[((size_t)b * HW + p0 + r) * 256 + ww] = *(uint32_t*)(ot + r * 1028 + ww * 4);
    }
    if (ppart) {
        float s2 = sacc[t * 2] + sacc[t * 2 + 1];
        ppart[((size_t)b * Cc + t) * 256 + pt] = s2;
    }
}

// ---------------- A prep ----------------
__global__ void __launch_bounds__(256) aprep_k(const float* __restrict__ W,
                                               const float* __restrict__ bias,
                                               const float* __restrict__ sc,
                                               const float* __restrict__ sh,
                                               __nv_bfloat16* __restrict__ A,
                                               float* __restrict__ bias2) {
    int b = blockIdx.x, o = threadIdx.x;
    float acc = __ldg(&bias[o]);
    __nv_bfloat16* row = A + ((size_t)b * 256 + o) * 512;
    for (int c = 0; c < 256; c++) {
        float w = __ldg(&W[o * 256 + c]);
        float s = sc ? w * sc[b * Cc + c] : w;
        __nv_bfloat16 hi = __float2bfloat16(s);
        __nv_bfloat16 lo = __float2bfloat16(s - __bfloat162float(hi));
        row[c] = hi; row[256 + c] = lo;
        if (sh) acc += w * sh[b * Cc + c];
    }
    bias2[b * Cc + o] = acc;
}

// ---------------- bf16 split GEMM via mma.sync (HMMA tensor pipe) ----------
// out[b][o][p] = sum over 3 segs: Ahi*Bhi + Ahi*Blo + Alo*Bhi (K_eff=768)
// A [b][256][512], Xc [b][16384][512], both K-major bf16 (hi|lo cols).
// CTA tile: 128 o x 128 p, BK=64, 3-stage cp.async pipeline.
__device__ __forceinline__ void load_chunk(int i, int t, uint32_t sb,
                                           const __nv_bfloat16* Ab,
                                           const __nv_bfloat16* Bbp) {
    int seg = i >> 2, kk = (i & 3) * 64;
    int a_col = (seg == 2 ? 256 : 0) + kk;
    int b_col = (seg == 1 ? 256 : 0) + kk;
    uint32_t abase = sb + (i % 3) * 32768;
    uint32_t bbase = abase + 16384;
    int row = t >> 3, k8 = t & 7;
#pragma unroll
    for (int j = 0; j < 4; j++) {
        int r = row + j * 32;
        CP_ASYNC16(abase + SWZ128(r * 128 + k8 * 16), Ab + (size_t)r * 512 + a_col + k8 * 8);
        CP_ASYNC16(bbase + SWZ128(r * 128 + k8 * 16), Bbp + (size_t)r * 512 + b_col + k8 * 8);
    }
}

__global__ void __launch_bounds__(256) gemm_k(
    const __nv_bfloat16* __restrict__ A, const __nv_bfloat16* __restrict__ Xc,
    const float* __restrict__ bias2, float* __restrict__ out,
    int epi, const float* __restrict__ echan, const float* __restrict__ res) {

    extern __shared__ __align__(1024) char sm[];
    uint32_t sb = smem_u32(sm);
    int t = threadIdx.x, lane = t & 31, w = t >> 5;
    int wm = w >> 2, wn = w & 3;                  // warp grid 2 x 4
    int o0 = blockIdx.x * 128, p0 = blockIdx.y * 128, b = blockIdx.z;
    const __nv_bfloat16* Ab  = A  + ((size_t)b * 256 + o0) * 512;
    const __nv_bfloat16* Bbp = Xc + ((size_t)b * HW  + p0) * 512;

    load_chunk(0, t, sb, Ab, Bbp); CP_COMMIT();
    load_chunk(1, t, sb, Ab, Bbp); CP_COMMIT();

    float acc[4][4][4];
#pragma unroll
    for (int mi = 0; mi < 4; mi++)
#pragma unroll
        for (int ni = 0; ni < 4; ni++)
#pragma unroll
            for (int q = 0; q < 4; q++) acc[mi][ni][q] = 0.f;

#pragma unroll
    for (int i = 0; i < 12; i++) {
        if (i == 11) { CP_WAIT0(); } else { CP_WAIT1(); }
        __syncthreads();
        if (i + 2 < 12) { load_chunk(i + 2, t, sb, Ab, Bbp); CP_COMMIT(); }

        uint32_t as = sb + (i % 3) * 32768, bs = as + 16384;
#pragma unroll
        for (int k2 = 0; k2 < 4; k2++) {
            uint32_t a[4][4];
#pragma unroll
            for (int mi = 0; mi < 4; mi++) {
                int r  = wm * 64 + mi * 16 + (lane & 15);
                int ch = k2 * 2 + (lane >> 4);
                ldsm4(a[mi][0], a[mi][1], a[mi][2], a[mi][3],
                      as + r * 128 + ((ch ^ (r & 7)) * 16));
            }
            uint32_t bb[2][4];
#pragma unroll
            for (int h = 0; h < 2; h++) {
                int r  = wn * 32 + h * 16 + ((lane >> 4) & 1) * 8 + (lane & 7);
                int ch = k2 * 2 + ((lane >> 3) & 1);
                ldsm4(bb[h][0], bb[h][1], bb[h][2], bb[h][3],
                      bs + r * 128 + ((ch ^ (r & 7)) * 16));
            }
#pragma unroll
            for (int mi = 0; mi < 4; mi++)
#pragma unroll
                for (int ni = 0; ni < 4; ni++) {
                    int h = ni >> 1, q = (ni & 1) * 2;
                    mma16816(acc[mi][ni], a[mi][0], a[mi][1], a[mi][2], a[mi][3],
                             bb[h][q], bb[h][q + 1]);
                }
        }
        __syncthreads();
    }

    // epilogue
    int g = lane >> 2, i4 = lane & 3;
#pragma unroll
    for (int mi = 0; mi < 4; mi++) {
        int o = o0 + wm * 64 + mi * 16 + g;
        float bv0 = bias2[b * Cc + o], bv1 = bias2[b * Cc + o + 8];
        float e0 = 1.f, e1 = 1.f;
        if (epi) { e0 = __ldg(&echan[o]); e1 = __ldg(&echan[o + 8]); }
        size_t r0b = (size_t)b * CHW + (size_t)o * HW;
        size_t r1b = r0b + (size_t)8 * HW;
#pragma unroll
        for (int ni = 0; ni < 4; ni++) {
            int p = p0 + wn * 32 + ni * 8 + i4 * 2;
            float2 y0, y1;
            y0.x = acc[mi][ni][0] + bv0; y0.y = acc[mi][ni][1] + bv0;
            y1.x = acc[mi][ni][2] + bv1; y1.y = acc[mi][ni][3] + bv1;
            if (epi) {
                float2 q0 = *(const float2*)(res + r0b + p);
                float2 q1 = *(const float2*)(res + r1b + p);
                y0.x = y0.x * e0 + q0.x; y0.y = y0.y * e0 + q0.y;
                y1.x = y1.x * e1 + q1.x; y1.y = y1.y * e1 + q1.y;
            }
            *(float2*)(out + r0b + p) = y0;
            *(float2*)(out + r1b + p) = y1;
        }
    }
}

// ---------------- depthwise 3x3 ----------------
__global__ void __launch_bounds__(256) dw3x3_k(const float* __restrict__ in,
                                               const float* __restrict__ w2,
                                               const float* __restrict__ b2,
                                               float* __restrict__ out) {
    __shared__ float s[34][128];
    int t = threadIdx.x;
    int b = blockIdx.z, c = blockIdx.y;
    int r0 = blockIdx.x * 32;
    size_t base = (size_t)b * CHW + (size_t)c * HW;
#pragma unroll
    for (int it = 0; it < 17; it++) {
        int idx = it * 256 + t;
        int rr = idx >> 7, cc = idx & 127;
        int gr = r0 - 1 + rr;
        s[rr][cc] = (gr >= 0 && gr < Hh) ? in[base + (size_t)gr * Wwid + cc] : 0.f;
    }
    float wv[9];
#pragma unroll
    for (int i = 0; i < 9; i++) wv[i] = __ldg(&w2[c * 9 + i]);
    float bias = __ldg(&b2[c]);
    __syncthreads();
#pragma unroll
    for (int it = 0; it < 16; it++) {
        int idx = it * 256 + t;
        int r = idx >> 7, cc = idx & 127;
        int sr = r + 1;
        float sum = bias;
#pragma unroll
        for (int dy = 0; dy < 3; dy++) {
            float l = (cc > 0)   ? s[sr - 1 + dy][cc - 1] : 0.f;
            float m = s[sr - 1 + dy][cc];
            float rr = (cc < 127) ? s[sr - 1 + dy][cc + 1] : 0.f;
            sum += wv[dy * 3 + 0] * l + wv[dy * 3 + 1] * m + wv[dy * 3 + 2] * rr;
        }
        out[base + (size_t)(r0 + r) * Wwid + cc] = sum;
    }
}

// ---------------- channel attention ----------------
__global__ void __launch_bounds__(256) att_k(const float* __restrict__ ppart,
                                             const float* __restrict__ wsca,
                                             const float* __restrict__ bsca,
                                             float* __restrict__ att) {
    __shared__ float sp[256];
    int b = blockIdx.x, t = threadIdx.x;
    float s = 0.f;
    const float* pr = ppart + ((size_t)b * Cc + t) * 256;
#pragma unroll 8
    for (int j = 0; j < 256; j++) s += pr[j];
    sp[t] = s * (1.f / (float)HW);
    __syncthreads();
    float acc = __ldg(&bsca[t]);
    const float* wrow = wsca + (size_t)t * 256;
    for (int c = 0; c < 256; c++) acc += sp[c] * __ldg(&wrow[c]);
    att[b * Cc + t] = acc;
}

// ---------------- launch ----------------
extern "C" void kernel_launch(void* const* d_in, const int* in_sizes, int n_in,
                              void* d_out, int out_size) {
    const float* x     = (const float*)d_in[0];
    const float* gn1_w = (const float*)d_in[1];
    const float* gn1_b = (const float*)d_in[2];
    const float* w1    = (const float*)d_in[3];
    const float* b1    = (const float*)d_in[4];
    const float* w2    = (const float*)d_in[5];
    const float* b2    = (const float*)d_in[6];
    const float* wg1   = (const float*)d_in[7];
    const float* bg1   = (const float*)d_in[8];
    const float* w_sca = (const float*)d_in[9];
    const float* b_sca = (const float*)d_in[10];
    const float* w3    = (const float*)d_in[11];
    const float* b3    = (const float*)d_in[12];
    const float* gn2_w = (const float*)d_in[13];
    const float* gn2_b = (const float*)d_in[14];
    const float* w4    = (const float*)d_in[15];
    const float* b4    = (const float*)d_in[16];
    const float* wg2   = (const float*)d_in[17];
    const float* bg2   = (const float*)d_in[18];
    const float* w5    = (const float*)d_in[19];
    const float* b5    = (const float*)d_in[20];
    const float* beta  = (const float*)d_in[21];
    const float* gamma = (const float*)d_in[22];
    float* out = (float*)d_out;

    float *bufA, *bufB, *bufX1, *ppart, *scl, *shf, *attv, *bias2;
    __nv_bfloat16 *XcA, *XcB, *Abuf;
    double* part;
    cudaGetSymbolAddress((void**)&bufA,  g_bufA);
    cudaGetSymbolAddress((void**)&bufB,  g_bufB);
    cudaGetSymbolAddress((void**)&bufX1, g_bufX1);
    cudaGetSymbolAddress((void**)&XcA,   g_XcA);
    cudaGetSymbolAddress((void**)&XcB,   g_XcB);
    cudaGetSymbolAddress((void**)&Abuf,  g_Abuf);
    cudaGetSymbolAddress((void**)&bias2, g_bias2);
    cudaGetSymbolAddress((void**)&part,  g_part);
    cudaGetSymbolAddress((void**)&ppart, g_ppart);
    cudaGetSymbolAddress((void**)&scl,   g_scale);
    cudaGetSymbolAddress((void**)&shf,   g_shift);
    cudaGetSymbolAddress((void**)&attv,  g_att);

    const int GEMM_SMEM = 3 * 32768;
    const int PREP_SMEM = 64 * 1028 + 256 * 4 + 512 * 4;
    cudaFuncSetAttribute(gemm_k, cudaFuncAttributeMaxDynamicSharedMemorySize, GEMM_SMEM);
    cudaFuncSetAttribute(prep_k, cudaFuncAttributeMaxDynamicSharedMemorySize, PREP_SMEM);

    dim3 ggrid(2, 128, Bb);
    dim3 pgrid(256, Bb);
    dim3 dgrid(4, Cc, Bb);
    dim3 sgrid(NBLK, Bb);

    // ---- path 1 ----
    stats1_k<<<sgrid, 256>>>(x, part);
    stats2_k<<<Bb, 256>>>(part, gn1_w, gn1_b, scl, shf);
    prep_k<<<pgrid, 256, PREP_SMEM>>>(x, nullptr, nullptr, XcA, nullptr, 0);
    aprep_k<<<Bb, 256>>>(w1, b1, scl, shf, Abuf, bias2);
    gemm_k<<<ggrid, 256, GEMM_SMEM>>>(Abuf, XcA, bias2, bufA, 0, nullptr, nullptr);
    dw3x3_k<<<dgrid, 256>>>(bufA, w2, b2, bufB);
    prep_k<<<pgrid, 256, PREP_SMEM>>>(bufB, wg1, bg1, XcB, ppart, 1);
    att_k<<<Bb, 256>>>(ppart, w_sca, b_sca, attv);
    aprep_k<<<Bb, 256>>>(w3, b3, attv, nullptr, Abuf, bias2);
    gemm_k<<<ggrid, 256, GEMM_SMEM>>>(Abuf, XcB, bias2, bufX1, 1, beta, x);

    // ---- path 2 ----
    stats1_k<<<sgrid, 256>>>(bufX1, part);
    stats2_k<<<Bb, 256>>>(part, gn2_w, gn2_b, scl, shf);
    prep_k<<<pgrid, 256, PREP_SMEM>>>(bufX1, nullptr, nullptr, XcA, nullptr, 0);
    aprep_k<<<Bb, 256>>>(w4, b4, scl, shf, Abuf, bias2);
    gemm_k<<<ggrid, 256, GEMM_SMEM>>>(Abuf, XcA, bias2, bufA, 0, nullptr, nullptr);
    prep_k<<<pgrid, 256, PREP_SMEM>>>(bufA, wg2, bg2, XcB, nullptr, 1);
    aprep_k<<<Bb, 256>>>(w5, b5, nullptr, nullptr, Abuf, bias2);
    gemm_k<<<ggrid, 256, GEMM_SMEM>>>(Abuf, XcB, bias2, out, 1, gamma, bufX1);
}

// round 4
// speedup vs baseline: 1.7543x; 1.7543x over previous
#include <cuda_runtime.h>
#include <cuda_bf16.h>
#include <math.h>
#include <stdint.h>

#define Cc   256
#define Hh   128
#define Wwid 128
#define HW   16384
#define CHW  4194304
#define Bb   8
#define NBLK 128

// ---------------- static scratch ----------------
__device__ __align__(1024) float  g_bufA[(size_t)Bb * CHW];
__device__ __align__(1024) float  g_bufB[(size_t)Bb * CHW];
__device__ __align__(1024) float  g_bufX1[(size_t)Bb * CHW];
__device__ __align__(1024) __nv_bfloat16 g_XcA[(size_t)Bb * HW * 512];
__device__ __align__(1024) __nv_bfloat16 g_XcB[(size_t)Bb * HW * 512];
__device__ __align__(1024) __nv_bfloat16 g_Abuf[(size_t)Bb * 256 * 512];
__device__ float  g_bias2[Bb * Cc];
__device__ double g_part[Bb * NBLK * 2];
__device__ float  g_ppart[(size_t)Bb * Cc * 256];
__device__ float  g_scale[Bb * Cc];
__device__ float  g_shift[Bb * Cc];
__device__ float  g_att[Bb * Cc];

__device__ __forceinline__ float gelu1(float x) {
    return 0.5f * x * (1.0f + erff(x * 0.70710678118654752440f));
}

// ---------------- PTX helpers ----------------
__device__ __forceinline__ uint32_t smem_u32(const void* p) {
    uint32_t a;
    asm("{ .reg .u64 t; cvta.to.shared.u64 t, %1; cvt.u32.u64 %0, t; }" : "=r"(a) : "l"(p));
    return a;
}
#define SWZ128(off) ((off) ^ (((off) >> 3) & 0x70))
#define CP_ASYNC16(sa, g) asm volatile("cp.async.cg.shared.global [%0], [%1], 16;" :: "r"(sa), "l"(g) : "memory")
#define CP_COMMIT() asm volatile("cp.async.commit_group;" ::: "memory")
#define CP_WAIT1()  asm volatile("cp.async.wait_group 1;" ::: "memory")
#define CP_WAIT0()  asm volatile("cp.async.wait_group 0;" ::: "memory")

__device__ __forceinline__ void ldsm4(uint32_t& r0, uint32_t& r1, uint32_t& r2, uint32_t& r3,
                                      uint32_t a) {
    asm volatile("ldmatrix.sync.aligned.m8n8.x4.shared.b16 {%0,%1,%2,%3}, [%4];"
                 : "=r"(r0), "=r"(r1), "=r"(r2), "=r"(r3) : "r"(a));
}
__device__ __forceinline__ void mma16816(float* c, uint32_t a0, uint32_t a1, uint32_t a2,
                                         uint32_t a3, uint32_t b0, uint32_t b1) {
    asm volatile("mma.sync.aligned.m16n8k16.row.col.f32.bf16.bf16.f32 "
                 "{%0,%1,%2,%3}, {%4,%5,%6,%7}, {%8,%9}, {%0,%1,%2,%3};"
                 : "+f"(c[0]), "+f"(c[1]), "+f"(c[2]), "+f"(c[3])
                 : "r"(a0), "r"(a1), "r"(a2), "r"(a3), "r"(b0), "r"(b1));
}

// ---------------- stats ----------------
__global__ void __launch_bounds__(256) stats1_k(const float* __restrict__ in,
                                                double* __restrict__ part) {
    int b = blockIdx.y, blk = blockIdx.x, t = threadIdx.x;
    size_t base = (size_t)b * CHW + (size_t)blk * (CHW / NBLK);
    double s = 0.0, s2 = 0.0;
    for (int i = t; i < CHW / NBLK; i += 256) {
        float x = in[base + i];
        s += (double)x; s2 += (double)x * (double)x;
    }
    __shared__ double ss[256], ss2[256];
    ss[t] = s; ss2[t] = s2;
    __syncthreads();
    for (int off = 128; off > 0; off >>= 1) {
        if (t < off) { ss[t] += ss[t + off]; ss2[t] += ss2[t + off]; }
        __syncthreads();
    }
    if (t == 0) {
        part[(b * NBLK + blk) * 2 + 0] = ss[0];
        part[(b * NBLK + blk) * 2 + 1] = ss2[0];
    }
}

__global__ void __launch_bounds__(256) stats2_k(const double* __restrict__ part,
                                                const float* __restrict__ gw,
                                                const float* __restrict__ gb,
                                                float* __restrict__ scale,
                                                float* __restrict__ shift) {
    int b = blockIdx.x, t = threadIdx.x;
    __shared__ double ss[128], ss2[128];
    __shared__ float smean, srstd;
    if (t < 128) {
        ss[t]  = part[(b * NBLK + t) * 2 + 0];
        ss2[t] = part[(b * NBLK + t) * 2 + 1];
    }
    __syncthreads();
    for (int off = 64; off > 0; off >>= 1) {
        if (t < off) { ss[t] += ss[t + off]; ss2[t] += ss2[t + off]; }
        __syncthreads();
    }
    if (t == 0) {
        double m = ss[0] / (double)CHW;
        double v = ss2[0] / (double)CHW - m * m;
        smean = (float)m;
        srstd = rsqrtf((float)v + 1e-5f);
    }
    __syncthreads();
    float sc = srstd * gw[t];
    scale[b * Cc + t] = sc;
    shift[b * Cc + t] = gb[t] - smean * sc;
}

// ---------------- prep: (optional gelu^2 + grouped 1x1) -> transpose -> bf16 split
// Each thread owns one pixel (pp) and a quarter of the groups (gq); computes all
// 4 channels of each group locally — no intra-loop __syncthreads.
__global__ void __launch_bounds__(256) prep_k(const float* __restrict__ in,
                                              const float* __restrict__ wg,
                                              const float* __restrict__ bg,
                                              __nv_bfloat16* __restrict__ out,
                                              float* __restrict__ ppart,
                                              int do_gelu) {
    extern __shared__ __align__(16) char sm[];
    char* ot = sm;                              // 64 px rows x 1028 bytes
    float* sacc = (float*)(sm + 64 * 1028);     // 512 floats
    int t = threadIdx.x;
    int b = blockIdx.y, pt = blockIdx.x;
    int p0 = pt * 64;
    int gq = t >> 6, pp = t & 63;
    size_t ibase = (size_t)b * CHW + p0 + pp;

#pragma unroll 4
    for (int gi = 0; gi < 16; gi++) {
        int g = gq * 16 + gi;
        int c0 = g * 4;
        float v[4];
#pragma unroll
        for (int i = 0; i < 4; i++) {
            float x = in[ibase + (size_t)(c0 + i) * HW];
            v[i] = do_gelu ? gelu1(gelu1(x)) : x;
        }
        float u[4];
        if (wg) {
#pragma unroll
            for (int o = 0; o < 4; o++) {
                float s = __ldg(&bg[c0 + o]);
#pragma unroll
                for (int i = 0; i < 4; i++) s += __ldg(&wg[g * 16 + o * 4 + i]) * v[i];
                u[o] = s;
            }
        } else {
#pragma unroll
            for (int o = 0; o < 4; o++) u[o] = v[o];
        }
#pragma unroll
        for (int o = 0; o < 4; o++) {
            int c = c0 + o;
            __nv_bfloat16 hi = __float2bfloat16(u[o]);
            __nv_bfloat16 lo = __float2bfloat16(u[o] - __bfloat162float(hi));
            *(__nv_bfloat16*)(ot + pp * 1028 + c * 2) = hi;
            *(__nv_bfloat16*)(ot + pp * 1028 + (256 + c) * 2) = lo;
            if (ppart) {
                float s = u[o];
#pragma unroll
                for (int off = 16; off > 0; off >>= 1)
                    s += __shfl_down_sync(0xffffffffu, s, off);
                if ((t & 31) == 0) sacc[c * 2 + ((t >> 5) & 1)] = s;
            }
        }
    }
    __syncthreads();
    uint32_t* og = (uint32_t*)out;
#pragma unroll
    for (int w = 0; w < 64; w++) {
        int r = (w * 256 + t) >> 8, ww = t;
        og[((size_t)b * HW + p0 + r) * 256 + ww] = *(uint32_t*)(ot + r * 1028 + ww * 4);
    }
    if (ppart) {
        float s2 = sacc[t * 2] + sacc[t * 2 + 1];
        ppart[((size_t)b * Cc + t) * 256 + pt] = s2;
    }
}

// ---------------- A prep: one block per (o, b), threads over c ----------------
__global__ void __launch_bounds__(256) aprep_k(const float* __restrict__ W,
                                               const float* __restrict__ bias,
                                               const float* __restrict__ sc,
                                               const float* __restrict__ sh,
                                               __nv_bfloat16* __restrict__ A,
                                               float* __restrict__ bias2) {
    int o = blockIdx.x, b = blockIdx.y, t = threadIdx.x;
    float w = __ldg(&W[o * 256 + t]);
    float s = sc ? w * sc[b * Cc + t] : w;
    __nv_bfloat16 hi = __float2bfloat16(s);
    __nv_bfloat16 lo = __float2bfloat16(s - __bfloat162float(hi));
    __nv_bfloat16* row = A + ((size_t)b * 256 + o) * 512;
    row[t] = hi; row[256 + t] = lo;

    __shared__ float red[256];
    red[t] = sh ? w * sh[b * Cc + t] : 0.f;
    __syncthreads();
    for (int off = 128; off > 0; off >>= 1) {
        if (t < off) red[t] += red[t + off];
        __syncthreads();
    }
    if (t == 0) bias2[b * Cc + o] = __ldg(&bias[o]) + red[0];
}

// ---------------- bf16 split GEMM via mma.sync (HMMA tensor pipe) ----------
__device__ __forceinline__ void load_chunk(int i, int t, uint32_t sb,
                                           const __nv_bfloat16* Ab,
                                           const __nv_bfloat16* Bbp) {
    int seg = i >> 2, kk = (i & 3) * 64;
    int a_col = (seg == 2 ? 256 : 0) + kk;
    int b_col = (seg == 1 ? 256 : 0) + kk;
    uint32_t abase = sb + (i % 3) * 32768;
    uint32_t bbase = abase + 16384;
    int row = t >> 3, k8 = t & 7;
#pragma unroll
    for (int j = 0; j < 4; j++) {
        int r = row + j * 32;
        CP_ASYNC16(abase + SWZ128(r * 128 + k8 * 16), Ab + (size_t)r * 512 + a_col + k8 * 8);
        CP_ASYNC16(bbase + SWZ128(r * 128 + k8 * 16), Bbp + (size_t)r * 512 + b_col + k8 * 8);
    }
}

__global__ void __launch_bounds__(256) gemm_k(
    const __nv_bfloat16* __restrict__ A, const __nv_bfloat16* __restrict__ Xc,
    const float* __restrict__ bias2, float* __restrict__ out,
    int epi, const float* __restrict__ echan, const float* __restrict__ res) {

    extern __shared__ __align__(1024) char sm[];
    uint32_t sb = smem_u32(sm);
    int t = threadIdx.x, lane = t & 31, w = t >> 5;
    int wm = w >> 2, wn = w & 3;
    int o0 = blockIdx.x * 128, p0 = blockIdx.y * 128, b = blockIdx.z;
    const __nv_bfloat16* Ab  = A  + ((size_t)b * 256 + o0) * 512;
    const __nv_bfloat16* Bbp = Xc + ((size_t)b * HW  + p0) * 512;

    load_chunk(0, t, sb, Ab, Bbp); CP_COMMIT();
    load_chunk(1, t, sb, Ab, Bbp); CP_COMMIT();

    float acc[4][4][4];
#pragma unroll
    for (int mi = 0; mi < 4; mi++)
#pragma unroll
        for (int ni = 0; ni < 4; ni++)
#pragma unroll
            for (int q = 0; q < 4; q++) acc[mi][ni][q] = 0.f;

#pragma unroll
    for (int i = 0; i < 12; i++) {
        if (i == 11) { CP_WAIT0(); } else { CP_WAIT1(); }
        __syncthreads();
        if (i + 2 < 12) { load_chunk(i + 2, t, sb, Ab, Bbp); CP_COMMIT(); }

        uint32_t as = sb + (i % 3) * 32768, bs = as + 16384;
#pragma unroll
        for (int k2 = 0; k2 < 4; k2++) {
            uint32_t a[4][4];
#pragma unroll
            for (int mi = 0; mi < 4; mi++) {
                int r  = wm * 64 + mi * 16 + (lane & 15);
                int ch = k2 * 2 + (lane >> 4);
                ldsm4(a[mi][0], a[mi][1], a[mi][2], a[mi][3],
                      as + r * 128 + ((ch ^ (r & 7)) * 16));
            }
            uint32_t bb[2][4];
#pragma unroll
            for (int h = 0; h < 2; h++) {
                int r  = wn * 32 + h * 16 + ((lane >> 4) & 1) * 8 + (lane & 7);
                int ch = k2 * 2 + ((lane >> 3) & 1);
                ldsm4(bb[h][0], bb[h][1], bb[h][2], bb[h][3],
                      bs + r * 128 + ((ch ^ (r & 7)) * 16));
            }
#pragma unroll
            for (int mi = 0; mi < 4; mi++)
#pragma unroll
                for (int ni = 0; ni < 4; ni++) {
                    int h = ni >> 1, q = (ni & 1) * 2;
                    mma16816(acc[mi][ni], a[mi][0], a[mi][1], a[mi][2], a[mi][3],
                             bb[h][q], bb[h][q + 1]);
                }
        }
        __syncthreads();
    }

    int g = lane >> 2, i4 = lane & 3;
#pragma unroll
    for (int mi = 0; mi < 4; mi++) {
        int o = o0 + wm * 64 + mi * 16 + g;
        float bv0 = bias2[b * Cc + o], bv1 = bias2[b * Cc + o + 8];
        float e0 = 1.f, e1 = 1.f;
        if (epi) { e0 = __ldg(&echan[o]); e1 = __ldg(&echan[o + 8]); }
        size_t r0b = (size_t)b * CHW + (size_t)o * HW;
        size_t r1b = r0b + (size_t)8 * HW;
#pragma unroll
        for (int ni = 0; ni < 4; ni++) {
            int p = p0 + wn * 32 + ni * 8 + i4 * 2;
            float2 y0, y1;
            y0.x = acc[mi][ni][0] + bv0; y0.y = acc[mi][ni][1] + bv0;
            y1.x = acc[mi][ni][2] + bv1; y1.y = acc[mi][ni][3] + bv1;
            if (epi) {
                float2 q0 = *(const float2*)(res + r0b + p);
                float2 q1 = *(const float2*)(res + r1b + p);
                y0.x = y0.x * e0 + q0.x; y0.y = y0.y * e0 + q0.y;
                y1.x = y1.x * e1 + q1.x; y1.y = y1.y * e1 + q1.y;
            }
            *(float2*)(out + r0b + p) = y0;
            *(float2*)(out + r1b + p) = y1;
        }
    }
}

// ---------------- depthwise 3x3 ----------------
__global__ void __launch_bounds__(256) dw3x3_k(const float* __restrict__ in,
                                               const float* __restrict__ w2,
                                               const float* __restrict__ b2,
                                               float* __restrict__ out) {
    __shared__ float s[34][128];
    int t = threadIdx.x;
    int b = blockIdx.z, c = blockIdx.y;
    int r0 = blockIdx.x * 32;
    size_t base = (size_t)b * CHW + (size_t)c * HW;
#pragma unroll
    for (int it = 0; it < 17; it++) {
        int idx = it * 256 + t;
        int rr = idx >> 7, cc = idx & 127;
        int gr = r0 - 1 + rr;
        s[rr][cc] = (gr >= 0 && gr < Hh) ? in[base + (size_t)gr * Wwid + cc] : 0.f;
    }
    float wv[9];
#pragma unroll
    for (int i = 0; i < 9; i++) wv[i] = __ldg(&w2[c * 9 + i]);
    float bias = __ldg(&b2[c]);
    __syncthreads();
#pragma unroll
    for (int it = 0; it < 16; it++) {
        int idx = it * 256 + t;
        int r = idx >> 7, cc = idx & 127;
        int sr = r + 1;
        float sum = bias;
#pragma unroll
        for (int dy = 0; dy < 3; dy++) {
            float l = (cc > 0)   ? s[sr - 1 + dy][cc - 1] : 0.f;
            float m = s[sr - 1 + dy][cc];
            float rr = (cc < 127) ? s[sr - 1 + dy][cc + 1] : 0.f;
            sum += wv[dy * 3 + 0] * l + wv[dy * 3 + 1] * m + wv[dy * 3 + 2] * rr;
        }
        out[base + (size_t)(r0 + r) * Wwid + cc] = sum;
    }
}

// ---------------- channel attention ----------------
__global__ void __launch_bounds__(256) att_k(const float* __restrict__ ppart,
                                             const float* __restrict__ wsca,
                                             const float* __restrict__ bsca,
                                             float* __restrict__ att) {
    __shared__ float sp[256];
    int b = blockIdx.x, t = threadIdx.x;
    float s = 0.f;
    const float* pr = ppart + ((size_t)b * Cc + t) * 256;
#pragma unroll 8
    for (int j = 0; j < 256; j++) s += pr[j];
    sp[t] = s * (1.f / (float)HW);
    __syncthreads();
    float acc = __ldg(&bsca[t]);
    const float* wrow = wsca + (size_t)t * 256;
#pragma unroll 8
    for (int c = 0; c < 256; c++) acc += sp[c] * __ldg(&wrow[c]);
    att[b * Cc + t] = acc;
}

// ---------------- launch ----------------
extern "C" void kernel_launch(void* const* d_in, const int* in_sizes, int n_in,
                              void* d_out, int out_size) {
    const float* x     = (const float*)d_in[0];
    const float* gn1_w = (const float*)d_in[1];
    const float* gn1_b = (const float*)d_in[2];
    const float* w1    = (const float*)d_in[3];
    const float* b1    = (const float*)d_in[4];
    const float* w2    = (const float*)d_in[5];
    const float* b2    = (const float*)d_in[6];
    const float* wg1   = (const float*)d_in[7];
    const float* bg1   = (const float*)d_in[8];
    const float* w_sca = (const float*)d_in[9];
    const float* b_sca = (const float*)d_in[10];
    const float* w3    = (const float*)d_in[11];
    const float* b3    = (const float*)d_in[12];
    const float* gn2_w = (const float*)d_in[13];
    const float* gn2_b = (const float*)d_in[14];
    const float* w4    = (const float*)d_in[15];
    const float* b4    = (const float*)d_in[16];
    const float* wg2   = (const float*)d_in[17];
    const float* bg2   = (const float*)d_in[18];
    const float* w5    = (const float*)d_in[19];
    const float* b5    = (const float*)d_in[20];
    const float* beta  = (const float*)d_in[21];
    const float* gamma = (const float*)d_in[22];
    float* out = (float*)d_out;

    float *bufA, *bufB, *bufX1, *ppart, *scl, *shf, *attv, *bias2;
    __nv_bfloat16 *XcA, *XcB, *Abuf;
    double* part;
    cudaGetSymbolAddress((void**)&bufA,  g_bufA);
    cudaGetSymbolAddress((void**)&bufB,  g_bufB);
    cudaGetSymbolAddress((void**)&bufX1, g_bufX1);
    cudaGetSymbolAddress((void**)&XcA,   g_XcA);
    cudaGetSymbolAddress((void**)&XcB,   g_XcB);
    cudaGetSymbolAddress((void**)&Abuf,  g_Abuf);
    cudaGetSymbolAddress((void**)&bias2, g_bias2);
    cudaGetSymbolAddress((void**)&part,  g_part);
    cudaGetSymbolAddress((void**)&ppart, g_ppart);
    cudaGetSymbolAddress((void**)&scl,   g_scale);
    cudaGetSymbolAddress((void**)&shf,   g_shift);
    cudaGetSymbolAddress((void**)&attv,  g_att);

    const int GEMM_SMEM = 3 * 32768;
    const int PREP_SMEM = 64 * 1028 + 512 * 4;
    cudaFuncSetAttribute(gemm_k, cudaFuncAttributeMaxDynamicSharedMemorySize, GEMM_SMEM);
    cudaFuncSetAttribute(prep_k, cudaFuncAttributeMaxDynamicSharedMemorySize, PREP_SMEM);

    dim3 ggrid(2, 128, Bb);
    dim3 pgrid(256, Bb);
    dim3 agrid(256, Bb);
    dim3 dgrid(4, Cc, Bb);
    dim3 sgrid(NBLK, Bb);

    // ---- path 1 ----
    stats1_k<<<sgrid, 256>>>(x, part);
    stats2_k<<<Bb, 256>>>(part, gn1_w, gn1_b, scl, shf);
    prep_k<<<pgrid, 256, PREP_SMEM>>>(x, nullptr, nullptr, XcA, nullptr, 0);
    aprep_k<<<agrid, 256>>>(w1, b1, scl, shf, Abuf, bias2);
    gemm_k<<<ggrid, 256, GEMM_SMEM>>>(Abuf, XcA, bias2, bufA, 0, nullptr, nullptr);
    dw3x3_k<<<dgrid, 256>>>(bufA, w2, b2, bufB);
    prep_k<<<pgrid, 256, PREP_SMEM>>>(bufB, wg1, bg1, XcB, ppart, 1);
    att_k<<<Bb, 256>>>(ppart, w_sca, b_sca, attv);
    aprep_k<<<agrid, 256>>>(w3, b3, attv, nullptr, Abuf, bias2);
    gemm_k<<<ggrid, 256, GEMM_SMEM>>>(Abuf, XcB, bias2, bufX1, 1, beta, x);

    // ---- path 2 ----
    stats1_k<<<sgrid, 256>>>(bufX1, part);
    stats2_k<<<Bb, 256>>>(part, gn2_w, gn2_b, scl, shf);
    prep_k<<<pgrid, 256, PREP_SMEM>>>(bufX1, nullptr, nullptr, XcA, nullptr, 0);
    aprep_k<<<agrid, 256>>>(w4, b4, scl, shf, Abuf, bias2);
    gemm_k<<<ggrid, 256, GEMM_SMEM>>>(Abuf, XcA, bias2, bufA, 0, nullptr, nullptr);
    prep_k<<<pgrid, 256, PREP_SMEM>>>(bufA, wg2, bg2, XcB, nullptr, 1);
    aprep_k<<<agrid, 256>>>(w5, b5, nullptr, nullptr, Abuf, bias2);
    gemm_k<<<ggrid, 256, GEMM_SMEM>>>(Abuf, XcB, bias2, out, 1, gamma, bufX1);
}

// round 5
// speedup vs baseline: 2.1553x; 1.2286x over previous
#include <cuda_runtime.h>
#include <cuda_fp16.h>
#include <math.h>
#include <stdint.h>

#define Cc   256
#define Hh   128
#define Wwid 128
#define HW   16384
#define CHW  4194304
#define Bb   8
#define NBLK 128

// ---------------- static scratch ----------------
__device__ __align__(1024) __half g_bufAh[(size_t)Bb * CHW];   // conv1/conv4 out (fp16)
__device__ __align__(1024) __half g_bufBh[(size_t)Bb * CHW];   // dw3x3 out (fp16)
__device__ __align__(1024) float  g_bufX1[(size_t)Bb * CHW];   // x1 residual (fp32)
__device__ __align__(1024) __half g_XcA[(size_t)Bb * HW * 256]; // B operand, hi-only fp16
__device__ __align__(1024) __half g_XcB[(size_t)Bb * HW * 256];
__device__ __align__(1024) __half g_Abuf[(size_t)Bb * 256 * 512]; // A: hi|lo fp16
__device__ float  g_bias2[Bb * Cc];
__device__ double g_part[Bb * NBLK * 2];
__device__ float  g_ppart[(size_t)Bb * Cc * 256];
__device__ float  g_scale[Bb * Cc];
__device__ float  g_shift[Bb * Cc];
__device__ float  g_att[Bb * Cc];

__device__ __forceinline__ float gelu1(float x) {
    return 0.5f * x * (1.0f + erff(x * 0.70710678118654752440f));
}

// ---------------- PTX helpers ----------------
__device__ __forceinline__ uint32_t smem_u32(const void* p) {
    uint32_t a;
    asm("{ .reg .u64 t; cvta.to.shared.u64 t, %1; cvt.u32.u64 %0, t; }" : "=r"(a) : "l"(p));
    return a;
}
#define SWZ128(off) ((off) ^ (((off) >> 3) & 0x70))
#define CP_ASYNC16(sa, g) asm volatile("cp.async.cg.shared.global [%0], [%1], 16;" :: "r"(sa), "l"(g) : "memory")
#define CP_COMMIT() asm volatile("cp.async.commit_group;" ::: "memory")
#define CP_WAIT1()  asm volatile("cp.async.wait_group 1;" ::: "memory")
#define CP_WAIT0()  asm volatile("cp.async.wait_group 0;" ::: "memory")

__device__ __forceinline__ void ldsm4(uint32_t& r0, uint32_t& r1, uint32_t& r2, uint32_t& r3,
                                      uint32_t a) {
    asm volatile("ldmatrix.sync.aligned.m8n8.x4.shared.b16 {%0,%1,%2,%3}, [%4];"
                 : "=r"(r0), "=r"(r1), "=r"(r2), "=r"(r3) : "r"(a));
}
__device__ __forceinline__ void mma16816(float* c, uint32_t a0, uint32_t a1, uint32_t a2,
                                         uint32_t a3, uint32_t b0, uint32_t b1) {
    asm volatile("mma.sync.aligned.m16n8k16.row.col.f32.f16.f16.f32 "
                 "{%0,%1,%2,%3}, {%4,%5,%6,%7}, {%8,%9}, {%0,%1,%2,%3};"
                 : "+f"(c[0]), "+f"(c[1]), "+f"(c[2]), "+f"(c[3])
                 : "r"(a0), "r"(a1), "r"(a2), "r"(a3), "r"(b0), "r"(b1));
}

// ---------------- stats ----------------
__global__ void __launch_bounds__(256) stats1_k(const float* __restrict__ in,
                                                double* __restrict__ part) {
    int b = blockIdx.y, blk = blockIdx.x, t = threadIdx.x;
    size_t base = (size_t)b * CHW + (size_t)blk * (CHW / NBLK);
    double s = 0.0, s2 = 0.0;
    for (int i = t; i < CHW / NBLK; i += 256) {
        float x = in[base + i];
        s += (double)x; s2 += (double)x * (double)x;
    }
    __shared__ double ss[256], ss2[256];
    ss[t] = s; ss2[t] = s2;
    __syncthreads();
    for (int off = 128; off > 0; off >>= 1) {
        if (t < off) { ss[t] += ss[t + off]; ss2[t] += ss2[t + off]; }
        __syncthreads();
    }
    if (t == 0) {
        part[(b * NBLK + blk) * 2 + 0] = ss[0];
        part[(b * NBLK + blk) * 2 + 1] = ss2[0];
    }
}

__global__ void __launch_bounds__(256) stats2_k(const double* __restrict__ part,
                                                const float* __restrict__ gw,
                                                const float* __restrict__ gb,
                                                float* __restrict__ scale,
                                                float* __restrict__ shift) {
    int b = blockIdx.x, t = threadIdx.x;
    __shared__ double ss[128], ss2[128];
    __shared__ float smean, srstd;
    if (t < 128) {
        ss[t]  = part[(b * NBLK + t) * 2 + 0];
        ss2[t] = part[(b * NBLK + t) * 2 + 1];
    }
    __syncthreads();
    for (int off = 64; off > 0; off >>= 1) {
        if (t < off) { ss[t] += ss[t + off]; ss2[t] += ss2[t + off]; }
        __syncthreads();
    }
    if (t == 0) {
        double m = ss[0] / (double)CHW;
        double v = ss2[0] / (double)CHW - m * m;
        smean = (float)m;
        srstd = rsqrtf((float)v + 1e-5f);
    }
    __syncthreads();
    float sc = srstd * gw[t];
    scale[b * Cc + t] = sc;
    shift[b * Cc + t] = gb[t] - smean * sc;
}

// ---------------- prep: (optional gelu^2 + grouped 1x1) -> transpose -> fp16 hi
// out[b][p][c] fp16 (256 cols). Templated on input type (float or __half).
template <typename T>
__global__ void __launch_bounds__(256) prep_k(const T* __restrict__ in,
                                              const float* __restrict__ wg,
                                              const float* __restrict__ bg,
                                              __half* __restrict__ out,
                                              float* __restrict__ ppart,
                                              int do_gelu) {
    extern __shared__ __align__(16) char sm[];
    char* ot = sm;                              // 64 px rows x 516 bytes
    float* sacc = (float*)(sm + 64 * 516);      // 512 floats
    int t = threadIdx.x;
    int b = blockIdx.y, pt = blockIdx.x;
    int p0 = pt * 64;
    int gq = t >> 6, pp = t & 63;
    size_t ibase = (size_t)b * CHW + p0 + pp;

#pragma unroll 4
    for (int gi = 0; gi < 16; gi++) {
        int g = gq * 16 + gi;
        int c0 = g * 4;
        float v[4];
#pragma unroll
        for (int i = 0; i < 4; i++) {
            float x = (float)in[ibase + (size_t)(c0 + i) * HW];
            v[i] = do_gelu ? gelu1(gelu1(x)) : x;
        }
        float u[4];
        if (wg) {
#pragma unroll
            for (int o = 0; o < 4; o++) {
                float s = __ldg(&bg[c0 + o]);
#pragma unroll
                for (int i = 0; i < 4; i++) s += __ldg(&wg[g * 16 + o * 4 + i]) * v[i];
                u[o] = s;
            }
        } else {
#pragma unroll
            for (int o = 0; o < 4; o++) u[o] = v[o];
        }
#pragma unroll
        for (int o = 0; o < 4; o++) {
            int c = c0 + o;
            *(__half*)(ot + pp * 516 + c * 2) = __float2half(u[o]);
            if (ppart) {
                float s = u[o];
#pragma unroll
                for (int off = 16; off > 0; off >>= 1)
                    s += __shfl_down_sync(0xffffffffu, s, off);
                if ((t & 31) == 0) sacc[c * 2 + ((t >> 5) & 1)] = s;
            }
        }
    }
    __syncthreads();
    uint32_t* og = (uint32_t*)out;
#pragma unroll
    for (int it = 0; it < 32; it++) {
        int idx = it * 256 + t;
        int r = idx >> 7, ww = idx & 127;
        og[((size_t)b * HW + p0 + r) * 128 + ww] = *(uint32_t*)(ot + r * 516 + ww * 4);
    }
    if (ppart) {
        float s2 = sacc[t * 2] + sacc[t * 2 + 1];
        ppart[((size_t)b * Cc + t) * 256 + pt] = s2;
    }
}

// ---------------- A prep: A[b][o][c]=hi fp16, [256+c]=lo fp16 ----------------
__global__ void __launch_bounds__(256) aprep_k(const float* __restrict__ W,
                                               const float* __restrict__ bias,
                                               const float* __restrict__ sc,
                                               const float* __restrict__ sh,
                                               __half* __restrict__ A,
                                               float* __restrict__ bias2) {
    int o = blockIdx.x, b = blockIdx.y, t = threadIdx.x;
    float w = __ldg(&W[o * 256 + t]);
    float s = sc ? w * sc[b * Cc + t] : w;
    __half hi = __float2half(s);
    __half lo = __float2half(s - __half2float(hi));
    __half* row = A + ((size_t)b * 256 + o) * 512;
    row[t] = hi; row[256 + t] = lo;

    __shared__ float red[256];
    red[t] = sh ? w * sh[b * Cc + t] : 0.f;
    __syncthreads();
    for (int off = 128; off > 0; off >>= 1) {
        if (t < off) red[t] += red[t + off];
        __syncthreads();
    }
    if (t == 0) bias2[b * Cc + o] = __ldg(&bias[o]) + red[0];
}

// ---------------- fp16 2-term GEMM via mma.sync ----------------
// D = Ahi*B + Alo*B   (A [b][256][512]: hi|lo, B=Xc [b][16384][256] fp16)
// 8 chunks of K=64: a_col = i*64 (sweeps hi then lo), b_col = (i&3)*64.
__device__ __forceinline__ void load_chunk(int i, int t, uint32_t sb,
                                           const __half* Ab, const __half* Bbp) {
    int a_col = i * 64;
    int b_col = (i & 3) * 64;
    uint32_t abase = sb + (i % 3) * 32768;
    uint32_t bbase = abase + 16384;
    int row = t >> 3, k8 = t & 7;
#pragma unroll
    for (int j = 0; j < 4; j++) {
        int r = row + j * 32;
        CP_ASYNC16(abase + SWZ128(r * 128 + k8 * 16), Ab + (size_t)r * 512 + a_col + k8 * 8);
        CP_ASYNC16(bbase + SWZ128(r * 128 + k8 * 16), Bbp + (size_t)r * 256 + b_col + k8 * 8);
    }
}

__global__ void __launch_bounds__(256) gemm_k(
    const __half* __restrict__ A, const __half* __restrict__ Xc,
    const float* __restrict__ bias2, void* __restrict__ outv,
    int epi, const float* __restrict__ echan, const float* __restrict__ res) {

    extern __shared__ __align__(1024) char sm[];
    uint32_t sb = smem_u32(sm);
    int t = threadIdx.x, lane = t & 31, w = t >> 5;
    int wm = w >> 2, wn = w & 3;
    int o0 = blockIdx.x * 128, p0 = blockIdx.y * 128, b = blockIdx.z;
    const __half* Ab  = A  + ((size_t)b * 256 + o0) * 512;
    const __half* Bbp = Xc + ((size_t)b * HW  + p0) * 256;

    load_chunk(0, t, sb, Ab, Bbp); CP_COMMIT();
    load_chunk(1, t, sb, Ab, Bbp); CP_COMMIT();

    float acc[4][4][4];
#pragma unroll
    for (int mi = 0; mi < 4; mi++)
#pragma unroll
        for (int ni = 0; ni < 4; ni++)
#pragma unroll
            for (int q = 0; q < 4; q++) acc[mi][ni][q] = 0.f;

#pragma unroll
    for (int i = 0; i < 8; i++) {
        if (i == 7) { CP_WAIT0(); } else { CP_WAIT1(); }
        __syncthreads();
        if (i + 2 < 8) { load_chunk(i + 2, t, sb, Ab, Bbp); CP_COMMIT(); }

        uint32_t as = sb + (i % 3) * 32768, bs = as + 16384;
#pragma unroll
        for (int k2 = 0; k2 < 4; k2++) {
            uint32_t a[4][4];
#pragma unroll
            for (int mi = 0; mi < 4; mi++) {
                int r  = wm * 64 + mi * 16 + (lane & 15);
                int ch = k2 * 2 + (lane >> 4);
                ldsm4(a[mi][0], a[mi][1], a[mi][2], a[mi][3],
                      as + r * 128 + ((ch ^ (r & 7)) * 16));
            }
            uint32_t bb[2][4];
#pragma unroll
            for (int h = 0; h < 2; h++) {
                int r  = wn * 32 + h * 16 + ((lane >> 4) & 1) * 8 + (lane & 7);
                int ch = k2 * 2 + ((lane >> 3) & 1);
                ldsm4(bb[h][0], bb[h][1], bb[h][2], bb[h][3],
                      bs + r * 128 + ((ch ^ (r & 7)) * 16));
            }
#pragma unroll
            for (int mi = 0; mi < 4; mi++)
#pragma unroll
                for (int ni = 0; ni < 4; ni++) {
                    int h = ni >> 1, q = (ni & 1) * 2;
                    mma16816(acc[mi][ni], a[mi][0], a[mi][1], a[mi][2], a[mi][3],
                             bb[h][q], bb[h][q + 1]);
                }
        }
        __syncthreads();
    }

    int g = lane >> 2, i4 = lane & 3;
#pragma unroll
    for (int mi = 0; mi < 4; mi++) {
        int o = o0 + wm * 64 + mi * 16 + g;
        float bv0 = bias2[b * Cc + o], bv1 = bias2[b * Cc + o + 8];
        float e0 = 1.f, e1 = 1.f;
        if (epi) { e0 = __ldg(&echan[o]); e1 = __ldg(&echan[o + 8]); }
        size_t r0b = (size_t)b * CHW + (size_t)o * HW;
        size_t r1b = r0b + (size_t)8 * HW;
#pragma unroll
        for (int ni = 0; ni < 4; ni++) {
            int p = p0 + wn * 32 + ni * 8 + i4 * 2;
            float y00 = acc[mi][ni][0] + bv0, y01 = acc[mi][ni][1] + bv0;
            float y10 = acc[mi][ni][2] + bv1, y11 = acc[mi][ni][3] + bv1;
            if (epi) {
                float* out = (float*)outv;
                float2 q0 = *(const float2*)(res + r0b + p);
                float2 q1 = *(const float2*)(res + r1b + p);
                float2 z0, z1;
                z0.x = y00 * e0 + q0.x; z0.y = y01 * e0 + q0.y;
                z1.x = y10 * e1 + q1.x; z1.y = y11 * e1 + q1.y;
                *(float2*)(out + r0b + p) = z0;
                *(float2*)(out + r1b + p) = z1;
            } else {
                __half* out = (__half*)outv;
                __half2 h0, h1;
                h0.x = __float2half(y00); h0.y = __float2half(y01);
                h1.x = __float2half(y10); h1.y = __float2half(y11);
                *(__half2*)(out + r0b + p) = h0;
                *(__half2*)(out + r1b + p) = h1;
            }
        }
    }
}

// ---------------- depthwise 3x3 (fp16 in/out, fp32 math) ----------------
__global__ void __launch_bounds__(256) dw3x3_k(const __half* __restrict__ in,
                                               const float* __restrict__ w2,
                                               const float* __restrict__ b2,
                                               __half* __restrict__ out) {
    __shared__ float s[34][128];
    int t = threadIdx.x;
    int b = blockIdx.z, c = blockIdx.y;
    int r0 = blockIdx.x * 32;
    size_t base = (size_t)b * CHW + (size_t)c * HW;
#pragma unroll
    for (int it = 0; it < 17; it++) {
        int idx = it * 256 + t;
        int rr = idx >> 7, cc = idx & 127;
        int gr = r0 - 1 + rr;
        s[rr][cc] = (gr >= 0 && gr < Hh) ? __half2float(in[base + (size_t)gr * Wwid + cc]) : 0.f;
    }
    float wv[9];
#pragma unroll
    for (int i = 0; i < 9; i++) wv[i] = __ldg(&w2[c * 9 + i]);
    float bias = __ldg(&b2[c]);
    __syncthreads();
#pragma unroll
    for (int it = 0; it < 16; it++) {
        int idx = it * 256 + t;
        int r = idx >> 7, cc = idx & 127;
        int sr = r + 1;
        float sum = bias;
#pragma unroll
        for (int dy = 0; dy < 3; dy++) {
            float l = (cc > 0)   ? s[sr - 1 + dy][cc - 1] : 0.f;
            float m = s[sr - 1 + dy][cc];
            float rr = (cc < 127) ? s[sr - 1 + dy][cc + 1] : 0.f;
            sum += wv[dy * 3 + 0] * l + wv[dy * 3 + 1] * m + wv[dy * 3 + 2] * rr;
        }
        out[base + (size_t)(r0 + r) * Wwid + cc] = __float2half(sum);
    }
}

// ---------------- channel attention ----------------
__global__ void __launch_bounds__(256) att_k(const float* __restrict__ ppart,
                                             const float* __restrict__ wsca,
                                             const float* __restrict__ bsca,
                                             float* __restrict__ att) {
    __shared__ float sp[256];
    int b = blockIdx.x, t = threadIdx.x;
    float s = 0.f;
    const float* pr = ppart + ((size_t)b * Cc + t) * 256;
#pragma unroll 8
    for (int j = 0; j < 256; j++) s += pr[j];
    sp[t] = s * (1.f / (float)HW);
    __syncthreads();
    float acc = __ldg(&bsca[t]);
    const float* wrow = wsca + (size_t)t * 256;
#pragma unroll 8
    for (int c = 0; c < 256; c++) acc += sp[c] * __ldg(&wrow[c]);
    att[b * Cc + t] = acc;
}

// ---------------- launch ----------------
extern "C" void kernel_launch(void* const* d_in, const int* in_sizes, int n_in,
                              void* d_out, int out_size) {
    const float* x     = (const float*)d_in[0];
    const float* gn1_w = (const float*)d_in[1];
    const float* gn1_b = (const float*)d_in[2];
    const float* w1    = (const float*)d_in[3];
    const float* b1    = (const float*)d_in[4];
    const float* w2    = (const float*)d_in[5];
    const float* b2    = (const float*)d_in[6];
    const float* wg1   = (const float*)d_in[7];
    const float* bg1   = (const float*)d_in[8];
    const float* w_sca = (const float*)d_in[9];
    const float* b_sca = (const float*)d_in[10];
    const float* w3    = (const float*)d_in[11];
    const float* b3    = (const float*)d_in[12];
    const float* gn2_w = (const float*)d_in[13];
    const float* gn2_b = (const float*)d_in[14];
    const float* w4    = (const float*)d_in[15];
    const float* b4    = (const float*)d_in[16];
    const float* wg2   = (const float*)d_in[17];
    const float* bg2   = (const float*)d_in[18];
    const float* w5    = (const float*)d_in[19];
    const float* b5    = (const float*)d_in[20];
    const float* beta  = (const float*)d_in[21];
    const float* gamma = (const float*)d_in[22];
    float* out = (float*)d_out;

    float *bufX1, *ppart, *scl, *shf, *attv, *bias2;
    __half *bufAh, *bufBh, *XcA, *XcB, *Abuf;
    double* part;
    cudaGetSymbolAddress((void**)&bufAh, g_bufAh);
    cudaGetSymbolAddress((void**)&bufBh, g_bufBh);
    cudaGetSymbolAddress((void**)&bufX1, g_bufX1);
    cudaGetSymbolAddress((void**)&XcA,   g_XcA);
    cudaGetSymbolAddress((void**)&XcB,   g_XcB);
    cudaGetSymbolAddress((void**)&Abuf,  g_Abuf);
    cudaGetSymbolAddress((void**)&bias2, g_bias2);
    cudaGetSymbolAddress((void**)&part,  g_part);
    cudaGetSymbolAddress((void**)&ppart, g_ppart);
    cudaGetSymbolAddress((void**)&scl,   g_scale);
    cudaGetSymbolAddress((void**)&shf,   g_shift);
    cudaGetSymbolAddress((void**)&attv,  g_att);

    const int GEMM_SMEM = 3 * 32768;
    const int PREP_SMEM = 64 * 516 + 512 * 4;
    cudaFuncSetAttribute(gemm_k, cudaFuncAttributeMaxDynamicSharedMemorySize, GEMM_SMEM);
    cudaFuncSetAttribute(prep_k<float>,  cudaFuncAttributeMaxDynamicSharedMemorySize, PREP_SMEM);
    cudaFuncSetAttribute(prep_k<__half>, cudaFuncAttributeMaxDynamicSharedMemorySize, PREP_SMEM);

    dim3 ggrid(2, 128, Bb);
    dim3 pgrid(256, Bb);
    dim3 agrid(256, Bb);
    dim3 dgrid(4, Cc, Bb);
    dim3 sgrid(NBLK, Bb);

    // ---- path 1 ----
    stats1_k<<<sgrid, 256>>>(x, part);
    stats2_k<<<Bb, 256>>>(part, gn1_w, gn1_b, scl, shf);
    prep_k<float><<<pgrid, 256, PREP_SMEM>>>(x, nullptr, nullptr, XcA, nullptr, 0);
    aprep_k<<<agrid, 256>>>(w1, b1, scl, shf, Abuf, bias2);
    gemm_k<<<ggrid, 256, GEMM_SMEM>>>(Abuf, XcA, bias2, bufAh, 0, nullptr, nullptr);
    dw3x3_k<<<dgrid, 256>>>(bufAh, w2, b2, bufBh);
    prep_k<__half><<<pgrid, 256, PREP_SMEM>>>(bufBh, wg1, bg1, XcB, ppart, 1);
    att_k<<<Bb, 256>>>(ppart, w_sca, b_sca, attv);
    aprep_k<<<agrid, 256>>>(w3, b3, attv, nullptr, Abuf, bias2);
    gemm_k<<<ggrid, 256, GEMM_SMEM>>>(Abuf, XcB, bias2, bufX1, 1, beta, x);

    // ---- path 2 ----
    stats1_k<<<sgrid, 256>>>(bufX1, part);
    stats2_k<<<Bb, 256>>>(part, gn2_w, gn2_b, scl, shf);
    prep_k<float><<<pgrid, 256, PREP_SMEM>>>(bufX1, nullptr, nullptr, XcA, nullptr, 0);
    aprep_k<<<agrid, 256>>>(w4, b4, scl, shf, Abuf, bias2);
    gemm_k<<<ggrid, 256, GEMM_SMEM>>>(Abuf, XcA, bias2, bufAh, 0, nullptr, nullptr);
    prep_k<__half><<<pgrid, 256, PREP_SMEM>>>(bufAh, wg2, bg2, XcB, nullptr, 1);
    aprep_k<<<agrid, 256>>>(w5, b5, nullptr, nullptr, Abuf, bias2);
    gemm_k<<<ggrid, 256, GEMM_SMEM>>>(Abuf, XcB, bias2, out, 1, gamma, bufX1);
}

// round 6
// speedup vs baseline: 2.8484x; 1.3216x over previous
#include <cuda_runtime.h>
#include <cuda_fp16.h>
#include <math.h>
#include <stdint.h>

#define Cc   256
#define Hh   128
#define Wwid 128
#define HW   16384
#define CHW  4194304
#define Bb   8
#define NBLK 128

// ---------------- static scratch ----------------
__device__ __align__(1024) __half g_bufAh[(size_t)Bb * CHW];   // conv1/conv4 out (fp16)
__device__ __align__(1024) __half g_bufBh[(size_t)Bb * CHW];   // dw3x3 out (fp16)
__device__ __align__(1024) float  g_bufX1[(size_t)Bb * CHW];   // x1 residual (fp32)
__device__ __align__(1024) __half g_XcA[(size_t)Bb * HW * 256]; // B operand fp16
__device__ __align__(1024) __half g_XcB[(size_t)Bb * HW * 256];
__device__ __align__(1024) __half g_Abuf[(size_t)Bb * 256 * 256]; // A fp16
__device__ float  g_bias2[Bb * Cc];
__device__ double g_part[Bb * NBLK * 2];     // stats1 partials (path 1)
__device__ double g_part2[Bb * 256 * 2];     // gemm3 epilogue partials (path 2)
__device__ float  g_ppart[(size_t)Bb * Cc * 256];
__device__ float  g_scale[Bb * Cc];
__device__ float  g_shift[Bb * Cc];
__device__ float  g_att[Bb * Cc];

__device__ __forceinline__ float gelu1(float x) {
    return 0.5f * x * (1.0f + erff(x * 0.70710678118654752440f));
}

// ---------------- PTX helpers ----------------
__device__ __forceinline__ uint32_t smem_u32(const void* p) {
    uint32_t a;
    asm("{ .reg .u64 t; cvta.to.shared.u64 t, %1; cvt.u32.u64 %0, t; }" : "=r"(a) : "l"(p));
    return a;
}
#define SWZ128(off) ((off) ^ (((off) >> 3) & 0x70))
#define CP_ASYNC16(sa, g) asm volatile("cp.async.cg.shared.global [%0], [%1], 16;" :: "r"(sa), "l"(g) : "memory")
#define CP_COMMIT() asm volatile("cp.async.commit_group;" ::: "memory")
#define CP_WAIT1()  asm volatile("cp.async.wait_group 1;" ::: "memory")
#define CP_WAIT0()  asm volatile("cp.async.wait_group 0;" ::: "memory")

__device__ __forceinline__ void ldsm4(uint32_t& r0, uint32_t& r1, uint32_t& r2, uint32_t& r3,
                                      uint32_t a) {
    asm volatile("ldmatrix.sync.aligned.m8n8.x4.shared.b16 {%0,%1,%2,%3}, [%4];"
                 : "=r"(r0), "=r"(r1), "=r"(r2), "=r"(r3) : "r"(a));
}
__device__ __forceinline__ void mma16816(float* c, uint32_t a0, uint32_t a1, uint32_t a2,
                                         uint32_t a3, uint32_t b0, uint32_t b1) {
    asm volatile("mma.sync.aligned.m16n8k16.row.col.f32.f16.f16.f32 "
                 "{%0,%1,%2,%3}, {%4,%5,%6,%7}, {%8,%9}, {%0,%1,%2,%3};"
                 : "+f"(c[0]), "+f"(c[1]), "+f"(c[2]), "+f"(c[3])
                 : "r"(a0), "r"(a1), "r"(a2), "r"(a3), "r"(b0), "r"(b1));
}

// ---------------- stats (path 1 over x) ----------------
__global__ void __launch_bounds__(256) stats1_k(const float* __restrict__ in,
                                                double* __restrict__ part) {
    int b = blockIdx.y, blk = blockIdx.x, t = threadIdx.x;
    size_t base = (size_t)b * CHW + (size_t)blk * (CHW / NBLK);
    double s = 0.0, s2 = 0.0;
    for (int i = t; i < CHW / NBLK; i += 256) {
        float x = in[base + i];
        s += (double)x; s2 += (double)x * (double)x;
    }
    __shared__ double ss[256], ss2[256];
    ss[t] = s; ss2[t] = s2;
    __syncthreads();
    for (int off = 128; off > 0; off >>= 1) {
        if (t < off) { ss[t] += ss[t + off]; ss2[t] += ss2[t + off]; }
        __syncthreads();
    }
    if (t == 0) {
        part[(b * NBLK + blk) * 2 + 0] = ss[0];
        part[(b * NBLK + blk) * 2 + 1] = ss2[0];
    }
}

// generic partial reduce -> scale/shift (npart partials per batch)
template <int NPART>
__global__ void __launch_bounds__(256) stats2_k(const double* __restrict__ part,
                                                const float* __restrict__ gw,
                                                const float* __restrict__ gb,
                                                float* __restrict__ scale,
                                                float* __restrict__ shift) {
    int b = blockIdx.x, t = threadIdx.x;
    __shared__ double ss[256], ss2[256];
    __shared__ float smean, srstd;
    double s = 0.0, s2 = 0.0;
    for (int j = t; j < NPART; j += 256) {
        s  += part[(b * NPART + j) * 2 + 0];
        s2 += part[(b * NPART + j) * 2 + 1];
    }
    ss[t] = s; ss2[t] = s2;
    __syncthreads();
    for (int off = 128; off > 0; off >>= 1) {
        if (t < off) { ss[t] += ss[t + off]; ss2[t] += ss2[t + off]; }
        __syncthreads();
    }
    if (t == 0) {
        double m = ss[0] / (double)CHW;
        double v = ss2[0] / (double)CHW - m * m;
        smean = (float)m;
        srstd = rsqrtf((float)v + 1e-5f);
    }
    __syncthreads();
    float sc = srstd * gw[t];
    scale[b * Cc + t] = sc;
    shift[b * Cc + t] = gb[t] - smean * sc;
}

// ---------------- prep: (optional gelu^2 + grouped 1x1) -> transpose -> fp16
template <typename T>
__global__ void __launch_bounds__(256) prep_k(const T* __restrict__ in,
                                              const float* __restrict__ wg,
                                              const float* __restrict__ bg,
                                              __half* __restrict__ out,
                                              float* __restrict__ ppart,
                                              int do_gelu) {
    extern __shared__ __align__(16) char sm[];
    char* ot = sm;                              // 64 px rows x 516 bytes
    float* sacc = (float*)(sm + 64 * 516);      // 512 floats
    int t = threadIdx.x;
    int b = blockIdx.y, pt = blockIdx.x;
    int p0 = pt * 64;
    int gq = t >> 6, pp = t & 63;
    size_t ibase = (size_t)b * CHW + p0 + pp;

#pragma unroll 4
    for (int gi = 0; gi < 16; gi++) {
        int g = gq * 16 + gi;
        int c0 = g * 4;
        float v[4];
#pragma unroll
        for (int i = 0; i < 4; i++) {
            float x = (float)in[ibase + (size_t)(c0 + i) * HW];
            v[i] = do_gelu ? gelu1(gelu1(x)) : x;
        }
        float u[4];
        if (wg) {
#pragma unroll
            for (int o = 0; o < 4; o++) {
                float s = __ldg(&bg[c0 + o]);
#pragma unroll
                for (int i = 0; i < 4; i++) s += __ldg(&wg[g * 16 + o * 4 + i]) * v[i];
                u[o] = s;
            }
        } else {
#pragma unroll
            for (int o = 0; o < 4; o++) u[o] = v[o];
        }
#pragma unroll
        for (int o = 0; o < 4; o++) {
            int c = c0 + o;
            *(__half*)(ot + pp * 516 + c * 2) = __float2half(u[o]);
            if (ppart) {
                float s = u[o];
#pragma unroll
                for (int off = 16; off > 0; off >>= 1)
                    s += __shfl_down_sync(0xffffffffu, s, off);
                if ((t & 31) == 0) sacc[c * 2 + ((t >> 5) & 1)] = s;
            }
        }
    }
    __syncthreads();
    uint32_t* og = (uint32_t*)out;
#pragma unroll
    for (int it = 0; it < 32; it++) {
        int idx = it * 256 + t;
        int r = idx >> 7, ww = idx & 127;
        og[((size_t)b * HW + p0 + r) * 128 + ww] = *(uint32_t*)(ot + r * 516 + ww * 4);
    }
    if (ppart) {
        float s2 = sacc[t * 2] + sacc[t * 2 + 1];
        ppart[((size_t)b * Cc + t) * 256 + pt] = s2;
    }
}

// ---------------- A prep: single fp16 ----------------
__global__ void __launch_bounds__(256) aprep_k(const float* __restrict__ W,
                                               const float* __restrict__ bias,
                                               const float* __restrict__ sc,
                                               const float* __restrict__ sh,
                                               __half* __restrict__ A,
                                               float* __restrict__ bias2) {
    int o = blockIdx.x, b = blockIdx.y, t = threadIdx.x;
    float w = __ldg(&W[o * 256 + t]);
    float s = sc ? w * sc[b * Cc + t] : w;
    A[((size_t)b * 256 + o) * 256 + t] = __float2half(s);

    __shared__ float red[256];
    red[t] = sh ? w * sh[b * Cc + t] : 0.f;
    __syncthreads();
    for (int off = 128; off > 0; off >>= 1) {
        if (t < off) red[t] += red[t + off];
        __syncthreads();
    }
    if (t == 0) bias2[b * Cc + o] = __ldg(&bias[o]) + red[0];
}

// ---------------- fp16 GEMM via mma.sync (K=256, 4 chunks) ----------------
__device__ __forceinline__ void load_chunk(int i, int t, uint32_t sb,
                                           const __half* Ab, const __half* Bbp) {
    int col = i * 64;
    uint32_t abase = sb + (i % 3) * 32768;
    uint32_t bbase = abase + 16384;
    int row = t >> 3, k8 = t & 7;
#pragma unroll
    for (int j = 0; j < 4; j++) {
        int r = row + j * 32;
        CP_ASYNC16(abase + SWZ128(r * 128 + k8 * 16), Ab + (size_t)r * 256 + col + k8 * 8);
        CP_ASYNC16(bbase + SWZ128(r * 128 + k8 * 16), Bbp + (size_t)r * 256 + col + k8 * 8);
    }
}

__global__ void __launch_bounds__(256) gemm_k(
    const __half* __restrict__ A, const __half* __restrict__ Xc,
    const float* __restrict__ bias2, void* __restrict__ outv,
    int epi, const float* __restrict__ echan, const float* __restrict__ res,
    double* __restrict__ statp) {

    extern __shared__ __align__(1024) char sm[];
    uint32_t sb = smem_u32(sm);
    int t = threadIdx.x, lane = t & 31, w = t >> 5;
    int wm = w >> 2, wn = w & 3;
    int o0 = blockIdx.x * 128, p0 = blockIdx.y * 128, b = blockIdx.z;
    const __half* Ab  = A  + ((size_t)b * 256 + o0) * 256;
    const __half* Bbp = Xc + ((size_t)b * HW  + p0) * 256;

    load_chunk(0, t, sb, Ab, Bbp); CP_COMMIT();
    load_chunk(1, t, sb, Ab, Bbp); CP_COMMIT();

    float acc[4][4][4];
#pragma unroll
    for (int mi = 0; mi < 4; mi++)
#pragma unroll
        for (int ni = 0; ni < 4; ni++)
#pragma unroll
            for (int q = 0; q < 4; q++) acc[mi][ni][q] = 0.f;

#pragma unroll
    for (int i = 0; i < 4; i++) {
        if (i == 3) { CP_WAIT0(); } else { CP_WAIT1(); }
        __syncthreads();
        if (i + 2 < 4) { load_chunk(i + 2, t, sb, Ab, Bbp); CP_COMMIT(); }

        uint32_t as = sb + (i % 3) * 32768, bs = as + 16384;
#pragma unroll
        for (int k2 = 0; k2 < 4; k2++) {
            uint32_t a[4][4];
#pragma unroll
            for (int mi = 0; mi < 4; mi++) {
                int r  = wm * 64 + mi * 16 + (lane & 15);
                int ch = k2 * 2 + (lane >> 4);
                ldsm4(a[mi][0], a[mi][1], a[mi][2], a[mi][3],
                      as + r * 128 + ((ch ^ (r & 7)) * 16));
            }
            uint32_t bb[2][4];
#pragma unroll
            for (int h = 0; h < 2; h++) {
                int r  = wn * 32 + h * 16 + ((lane >> 4) & 1) * 8 + (lane & 7);
                int ch = k2 * 2 + ((lane >> 3) & 1);
                ldsm4(bb[h][0], bb[h][1], bb[h][2], bb[h][3],
                      bs + r * 128 + ((ch ^ (r & 7)) * 16));
            }
#pragma unroll
            for (int mi = 0; mi < 4; mi++)
#pragma unroll
                for (int ni = 0; ni < 4; ni++) {
                    int h = ni >> 1, q = (ni & 1) * 2;
                    mma16816(acc[mi][ni], a[mi][0], a[mi][1], a[mi][2], a[mi][3],
                             bb[h][q], bb[h][q + 1]);
                }
        }
        __syncthreads();
    }

    int g = lane >> 2, i4 = lane & 3;
    float ls = 0.f, ls2 = 0.f;
#pragma unroll
    for (int mi = 0; mi < 4; mi++) {
        int o = o0 + wm * 64 + mi * 16 + g;
        float bv0 = bias2[b * Cc + o], bv1 = bias2[b * Cc + o + 8];
        float e0 = 1.f, e1 = 1.f;
        if (epi) { e0 = __ldg(&echan[o]); e1 = __ldg(&echan[o + 8]); }
        size_t r0b = (size_t)b * CHW + (size_t)o * HW;
        size_t r1b = r0b + (size_t)8 * HW;
#pragma unroll
        for (int ni = 0; ni < 4; ni++) {
            int p = p0 + wn * 32 + ni * 8 + i4 * 2;
            float y00 = acc[mi][ni][0] + bv0, y01 = acc[mi][ni][1] + bv0;
            float y10 = acc[mi][ni][2] + bv1, y11 = acc[mi][ni][3] + bv1;
            if (epi) {
                float* out = (float*)outv;
                float2 q0 = *(const float2*)(res + r0b + p);
                float2 q1 = *(const float2*)(res + r1b + p);
                float2 z0, z1;
                z0.x = y00 * e0 + q0.x; z0.y = y01 * e0 + q0.y;
                z1.x = y10 * e1 + q1.x; z1.y = y11 * e1 + q1.y;
                *(float2*)(out + r0b + p) = z0;
                *(float2*)(out + r1b + p) = z1;
                if (statp) {
                    ls  += z0.x + z0.y + z1.x + z1.y;
                    ls2 += z0.x * z0.x + z0.y * z0.y + z1.x * z1.x + z1.y * z1.y;
                }
            } else {
                __half* out = (__half*)outv;
                __half2 h0, h1;
                h0.x = __float2half(y00); h0.y = __float2half(y01);
                h1.x = __float2half(y10); h1.y = __float2half(y11);
                *(__half2*)(out + r0b + p) = h0;
                *(__half2*)(out + r1b + p) = h1;
            }
        }
    }
    if (statp) {
        double* sd = (double*)sm;
        sd[t] = (double)ls; sd[256 + t] = (double)ls2;
        __syncthreads();
        for (int off = 128; off > 0; off >>= 1) {
            if (t < off) { sd[t] += sd[t + off]; sd[256 + t] += sd[256 + t + off]; }
            __syncthreads();
        }
        if (t == 0) {
            int idx = blockIdx.x + 2 * blockIdx.y;  // 0..255 within batch
            statp[((size_t)b * 256 + idx) * 2 + 0] = sd[0];
            statp[((size_t)b * 256 + idx) * 2 + 1] = sd[256];
        }
    }
}

// ---------------- depthwise 3x3 (fp16 in/out, fp32 math) ----------------
__global__ void __launch_bounds__(256) dw3x3_k(const __half* __restrict__ in,
                                               const float* __restrict__ w2,
                                               const float* __restrict__ b2,
                                               __half* __restrict__ out) {
    __shared__ float s[34][128];
    int t = threadIdx.x;
    int b = blockIdx.z, c = blockIdx.y;
    int r0 = blockIdx.x * 32;
    size_t base = (size_t)b * CHW + (size_t)c * HW;
#pragma unroll
    for (int it = 0; it < 17; it++) {
        int idx = it * 256 + t;
        int rr = idx >> 7, cc = idx & 127;
        int gr = r0 - 1 + rr;
        s[rr][cc] = (gr >= 0 && gr < Hh) ? __half2float(in[base + (size_t)gr * Wwid + cc]) : 0.f;
    }
    float wv[9];
#pragma unroll
    for (int i = 0; i < 9; i++) wv[i] = __ldg(&w2[c * 9 + i]);
    float bias = __ldg(&b2[c]);
    __syncthreads();
#pragma unroll
    for (int it = 0; it < 16; it++) {
        int idx = it * 256 + t;
        int r = idx >> 7, cc = idx & 127;
        int sr = r + 1;
        float sum = bias;
#pragma unroll
        for (int dy = 0; dy < 3; dy++) {
            float l = (cc > 0)   ? s[sr - 1 + dy][cc - 1] : 0.f;
            float m = s[sr - 1 + dy][cc];
            float rr = (cc < 127) ? s[sr - 1 + dy][cc + 1] : 0.f;
            sum += wv[dy * 3 + 0] * l + wv[dy * 3 + 1] * m + wv[dy * 3 + 2] * rr;
        }
        out[base + (size_t)(r0 + r) * Wwid + cc] = __float2half(sum);
    }
}

// ---------------- channel attention ----------------
__global__ void __launch_bounds__(256) att_k(const float* __restrict__ ppart,
                                             const float* __restrict__ wsca,
                                             const float* __restrict__ bsca,
                                             float* __restrict__ att) {
    __shared__ float sp[256];
    int b = blockIdx.x, t = threadIdx.x;
    float s = 0.f;
    const float* pr = ppart + ((size_t)b * Cc + t) * 256;
#pragma unroll 8
    for (int j = 0; j < 256; j++) s += pr[j];
    sp[t] = s * (1.f / (float)HW);
    __syncthreads();
    float acc = __ldg(&bsca[t]);
    const float* wrow = wsca + (size_t)t * 256;
#pragma unroll 8
    for (int c = 0; c < 256; c++) acc += sp[c] * __ldg(&wrow[c]);
    att[b * Cc + t] = acc;
}

// ---------------- launch ----------------
extern "C" void kernel_launch(void* const* d_in, const int* in_sizes, int n_in,
                              void* d_out, int out_size) {
    const float* x     = (const float*)d_in[0];
    const float* gn1_w = (const float*)d_in[1];
    const float* gn1_b = (const float*)d_in[2];
    const float* w1    = (const float*)d_in[3];
    const float* b1    = (const float*)d_in[4];
    const float* w2    = (const float*)d_in[5];
    const float* b2    = (const float*)d_in[6];
    const float* wg1   = (const float*)d_in[7];
    const float* bg1   = (const float*)d_in[8];
    const float* w_sca = (const float*)d_in[9];
    const float* b_sca = (const float*)d_in[10];
    const float* w3    = (const float*)d_in[11];
    const float* b3    = (const float*)d_in[12];
    const float* gn2_w = (const float*)d_in[13];
    const float* gn2_b = (const float*)d_in[14];
    const float* w4    = (const float*)d_in[15];
    const float* b4    = (const float*)d_in[16];
    const float* wg2   = (const float*)d_in[17];
    const float* bg2   = (const float*)d_in[18];
    const float* w5    = (const float*)d_in[19];
    const float* b5    = (const float*)d_in[20];
    const float* beta  = (const float*)d_in[21];
    const float* gamma = (const float*)d_in[22];
    float* out = (float*)d_out;

    float *bufX1, *ppart, *scl, *shf, *attv, *bias2;
    __half *bufAh, *bufBh, *XcA, *XcB, *Abuf;
    double *part, *part2;
    cudaGetSymbolAddress((void**)&bufAh, g_bufAh);
    cudaGetSymbolAddress((void**)&bufBh, g_bufBh);
    cudaGetSymbolAddress((void**)&bufX1, g_bufX1);
    cudaGetSymbolAddress((void**)&XcA,   g_XcA);
    cudaGetSymbolAddress((void**)&XcB,   g_XcB);
    cudaGetSymbolAddress((void**)&Abuf,  g_Abuf);
    cudaGetSymbolAddress((void**)&bias2, g_bias2);
    cudaGetSymbolAddress((void**)&part,  g_part);
    cudaGetSymbolAddress((void**)&part2, g_part2);
    cudaGetSymbolAddress((void**)&ppart, g_ppart);
    cudaGetSymbolAddress((void**)&scl,   g_scale);
    cudaGetSymbolAddress((void**)&shf,   g_shift);
    cudaGetSymbolAddress((void**)&attv,  g_att);

    const int GEMM_SMEM = 3 * 32768;
    const int PREP_SMEM = 64 * 516 + 512 * 4;
    cudaFuncSetAttribute(gemm_k, cudaFuncAttributeMaxDynamicSharedMemorySize, GEMM_SMEM);
    cudaFuncSetAttribute(prep_k<float>,  cudaFuncAttributeMaxDynamicSharedMemorySize, PREP_SMEM);
    cudaFuncSetAttribute(prep_k<__half>, cudaFuncAttributeMaxDynamicSharedMemorySize, PREP_SMEM);

    dim3 ggrid(2, 128, Bb);
    dim3 pgrid(256, Bb);
    dim3 agrid(256, Bb);
    dim3 dgrid(4, Cc, Bb);
    dim3 sgrid(NBLK, Bb);

    // ---- path 1 ----
    stats1_k<<<sgrid, 256>>>(x, part);
    stats2_k<NBLK><<<Bb, 256>>>(part, gn1_w, gn1_b, scl, shf);
    prep_k<float><<<pgrid, 256, PREP_SMEM>>>(x, nullptr, nullptr, XcA, nullptr, 0);
    aprep_k<<<agrid, 256>>>(w1, b1, scl, shf, Abuf, bias2);
    gemm_k<<<ggrid, 256, GEMM_SMEM>>>(Abuf, XcA, bias2, bufAh, 0, nullptr, nullptr, nullptr);
    dw3x3_k<<<dgrid, 256>>>(bufAh, w2, b2, bufBh);
    prep_k<__half><<<pgrid, 256, PREP_SMEM>>>(bufBh, wg1, bg1, XcB, ppart, 1);
    att_k<<<Bb, 256>>>(ppart, w_sca, b_sca, attv);
    aprep_k<<<agrid, 256>>>(w3, b3, attv, nullptr, Abuf, bias2);
    gemm_k<<<ggrid, 256, GEMM_SMEM>>>(Abuf, XcB, bias2, bufX1, 1, beta, x, part2);

    // ---- path 2 (GN2 stats came from gemm3 epilogue partials) ----
    stats2_k<256><<<Bb, 256>>>(part2, gn2_w, gn2_b, scl, shf);
    prep_k<float><<<pgrid, 256, PREP_SMEM>>>(bufX1, nullptr, nullptr, XcA, nullptr, 0);
    aprep_k<<<agrid, 256>>>(w4, b4, scl, shf, Abuf, bias2);
    gemm_k<<<ggrid, 256, GEMM_SMEM>>>(Abuf, XcA, bias2, bufAh, 0, nullptr, nullptr, nullptr);
    prep_k<__half><<<pgrid, 256, PREP_SMEM>>>(bufAh, wg2, bg2, XcB, nullptr, 1);
    aprep_k<<<agrid, 256>>>(w5, b5, nullptr, nullptr, Abuf, bias2);
    gemm_k<<<ggrid, 256, GEMM_SMEM>>>(Abuf, XcB, bias2, out, 1, gamma, bufX1, nullptr);
}